// round 12
// baseline (speedup 1.0000x reference)
#include <cuda_runtime.h>
#include <cuda_fp16.h>
#include <math.h>
#include <stdint.h>

#define HW    16384
#define WID   128
#define CCH   192
#define C3    576
#define NB    8
#define NHEAD 4
#define CH    48
#define EPSV  1e-12f

// ---------------- scratch (device globals; allocation-free) ----------------
__device__ __align__(16) __half g_cn1 [(size_t)NB*CCH*HW];
__device__ __align__(16) float  g_cnf [(size_t)NB*CCH*HW];
__device__ __align__(16) __half g_qkv1[(size_t)NB*C3 *HW];
__device__ __align__(16) float  g_qkv [(size_t)NB*C3 *HW];
__device__ __align__(16) uint32_t g_Wp3[(size_t)(CCH*9/2)*CCH];
__device__ __align__(16) uint32_t g_Wpq[(size_t)96*C3];     // packed qkv_w
__device__ __align__(16) uint32_t g_Wpc[(size_t)96*CCH];    // packed cn_w1
__device__ __align__(16) uint32_t g_Mp [(size_t)NB*96*CCH]; // packed proj@attn
__device__ float g_alpha[NB*CCH];
__device__ float g_beta [NB*CCH];
__device__ float g_invk [NB*CCH];
__device__ float g_Gqk [(size_t)16*32*CH*CH];
__device__ float g_Gck [(size_t)16*32*CH*CH];
__device__ float g_Np  [(size_t)16*32*4*CH];
__device__ float g_attn[(size_t)NB*NHEAD*CH*CH];

__device__ __forceinline__ uint32_t pack_h2(float lo, float hi) {
  __half2 h = __floats2half2_rn(lo, hi);
  return *(uint32_t*)&h;
}
__device__ __forceinline__ uint32_t pack_hh(__half lo, __half hi) {
  __half2 h = __halves2half2(lo, hi);
  return *(uint32_t*)&h;
}
__device__ __forceinline__ void store2(float* p, float a, float b) {
  *(float2*)p = make_float2(a, b);
}
__device__ __forceinline__ void store2(__half* p, float a, float b) {
  *(uint32_t*)p = pack_h2(a, b);
}
__device__ __forceinline__ void mma_fp16(float* c, const uint32_t* a, const uint32_t* b) {
  asm volatile(
    "mma.sync.aligned.m16n8k16.row.col.f32.f16.f16.f32 "
    "{%0,%1,%2,%3},{%4,%5,%6,%7},{%8,%9},{%0,%1,%2,%3};"
    : "+f"(c[0]), "+f"(c[1]), "+f"(c[2]), "+f"(c[3])
    : "r"(a[0]), "r"(a[1]), "r"(a[2]), "r"(a[3]), "r"(b[0]), "r"(b[1]));
}

#define AST 200
#define BST 136

// ------- pack 1x1 weights W[M][192] -> Wp[k2][M] (half2 pairs) --------------
__global__ __launch_bounds__(256) void wtrans1_k(
    const float* __restrict__ W, uint32_t* __restrict__ Wp, int M)
{
  int e = blockIdx.x * 256 + threadIdx.x;     // 96*M
  if (e >= 96 * M) return;
  int k2 = e / M, m = e - k2 * M;
  float a = W[(size_t)m * CCH + 2 * k2];
  float b = W[(size_t)m * CCH + 2 * k2 + 1];
  Wp[(size_t)k2 * M + m] = pack_h2(a, b);
}

// ======= fp16 tensor-core GEMM, prepacked weights, K=192 fixed ==============
// Y[b, m, n] = sum_k W[m,k] X_b[k,n].  CTA tile 192(M) x 128(N), BK=16.
template <typename OutT>
__global__ __launch_bounds__(256, 1) void gemm1x1p_fp16(
    const uint32_t* __restrict__ Wp, const float* __restrict__ X,
    OutT* __restrict__ Y, int M,
    size_t wstride, size_t xstride, size_t ystride)
{
  const int b  = blockIdx.z;
  const int m0 = blockIdx.y * 192;
  const int n0 = blockIdx.x * 128;
  const uint32_t* Wb = Wp + (size_t)b * wstride;
  const float* Xb = X + (size_t)b * xstride;
  OutT* Yb = Y + (size_t)b * ystride;

  __shared__ uint32_t As2[2][8][AST];
  __shared__ uint32_t Bs2[2][8][BST];

  const int t    = threadIdx.x;
  const int wid  = t >> 5, lane = t & 31;
  const int wm   = wid >> 1, wn = wid & 1;
  const int grp  = lane >> 2, t4 = lane & 3;

  float acc[3][8][4] = {};

  const int bk2 = t >> 5;          // 0..7
  const int bng = (t & 31) * 4;    // 0..124

  uint32_t paw[6];
  float4 pb0, pb1;
  #pragma unroll
  for (int i = 0; i < 6; i++) {
    int e = t + i * 256; int k2l = e / 192, m = e - k2l * 192;
    paw[i] = Wb[(size_t)k2l * M + m0 + m];
  }
  pb0 = *(const float4*)&Xb[(size_t)(2 * bk2    ) * HW + n0 + bng];
  pb1 = *(const float4*)&Xb[(size_t)(2 * bk2 + 1) * HW + n0 + bng];
  #pragma unroll
  for (int i = 0; i < 6; i++) {
    int e = t + i * 256; int k2l = e / 192, m = e - k2l * 192;
    As2[0][k2l][m] = paw[i];
  }
  {
    uint4 u = make_uint4(pack_h2(pb0.x, pb1.x), pack_h2(pb0.y, pb1.y),
                         pack_h2(pb0.z, pb1.z), pack_h2(pb0.w, pb1.w));
    *(uint4*)&Bs2[0][bk2][bng] = u;
  }
  __syncthreads();

  int p = 0;
  #pragma unroll 1
  for (int k0 = 0; k0 < 192; k0 += 16) {
    bool more = (k0 + 16) < 192;
    if (more) {
      int k2base = (k0 + 16) >> 1;
      #pragma unroll
      for (int i = 0; i < 6; i++) {
        int e = t + i * 256; int k2l = e / 192, m = e - k2l * 192;
        paw[i] = Wb[(size_t)(k2base + k2l) * M + m0 + m];
      }
      pb0 = *(const float4*)&Xb[(size_t)(k0 + 16 + 2 * bk2    ) * HW + n0 + bng];
      pb1 = *(const float4*)&Xb[(size_t)(k0 + 16 + 2 * bk2 + 1) * HW + n0 + bng];
    }
    {
      uint32_t af[3][4], bf[8][2];
      #pragma unroll
      for (int mt = 0; mt < 3; mt++) {
        int mb = wm * 48 + mt * 16 + grp;
        af[mt][0] = As2[p][t4    ][mb];     af[mt][1] = As2[p][t4    ][mb + 8];
        af[mt][2] = As2[p][t4 + 4][mb];     af[mt][3] = As2[p][t4 + 4][mb + 8];
      }
      #pragma unroll
      for (int nt = 0; nt < 8; nt++) {
        int nb = wn * 64 + nt * 8 + grp;
        bf[nt][0] = Bs2[p][t4][nb]; bf[nt][1] = Bs2[p][t4 + 4][nb];
      }
      #pragma unroll
      for (int mt = 0; mt < 3; mt++)
        #pragma unroll
        for (int nt = 0; nt < 8; nt++)
          mma_fp16(acc[mt][nt], af[mt], bf[nt]);
    }
    if (more) {
      #pragma unroll
      for (int i = 0; i < 6; i++) {
        int e = t + i * 256; int k2l = e / 192, m = e - k2l * 192;
        As2[1-p][k2l][m] = paw[i];
      }
      uint4 u = make_uint4(pack_h2(pb0.x, pb1.x), pack_h2(pb0.y, pb1.y),
                           pack_h2(pb0.z, pb1.z), pack_h2(pb0.w, pb1.w));
      *(uint4*)&Bs2[1-p][bk2][bng] = u;
    }
    __syncthreads();
    p ^= 1;
  }

  #pragma unroll
  for (int mt = 0; mt < 3; mt++) {
    #pragma unroll
    for (int nt = 0; nt < 8; nt++) {
      int mr = m0 + wm * 48 + mt * 16 + grp;
      int nc = n0 + wn * 64 + nt * 8 + t4 * 2;
      store2(&Yb[(size_t)mr * HW + nc], acc[mt][nt][0], acc[mt][nt][1]);
      store2(&Yb[(size_t)(mr + 8) * HW + nc], acc[mt][nt][2], acc[mt][nt][3]);
    }
  }
}

// ------- conv3 weight transform: W[m][ci*9+tap] -> packed Wp[k2][m] ---------
__global__ __launch_bounds__(256) void wtrans3_k(
    const float* __restrict__ W, uint32_t* __restrict__ Wp)
{
  int e = blockIdx.x * 256 + threadIdx.x;
  if (e >= (CCH*9/2) * CCH) return;
  int k2 = e / CCH, m = e - k2 * CCH;
  int k  = k2 * 2;
  int tap = k / CCH;
  int ci  = k - tap * CCH;
  float a = W[(size_t)m * (CCH*9) + ci * 9 + tap];
  float b = W[(size_t)m * (CCH*9) + (ci + 1) * 9 + tap];
  Wp[(size_t)k2 * CCH + m] = pack_h2(a, b);
}

// ====== fp16 conv3x3, reordered-K implicit GEMM, prepacked weights (R9) =====
__global__ __launch_bounds__(256, 1) void conv3x3_fp16(
    const uint32_t* __restrict__ Wp, const __half* __restrict__ X,
    float* __restrict__ Y)
{
  const int Ktot = CCH * 9;
  const int b = blockIdx.z;
  const int y = blockIdx.x;
  const __half* Xb = X + (size_t)b * CCH * HW;
  float* Yb = Y + (size_t)b * CCH * HW;

  __shared__ uint32_t As2[2][8][AST];
  __shared__ uint32_t Bs2[2][8][BST];

  const int t   = threadIdx.x;
  const int wid = t >> 5, lane = t & 31;
  const int wm  = wid >> 1, wn = wid & 1;
  const int grp = lane >> 2, t4 = lane & 3;

  float acc[3][8][4] = {};

  const int bk2 = t >> 5;
  const int bng = (t & 31) * 4;

  const __half hz = __float2half(0.f);

  auto gatherB = [&](int k0, uint4* u) {
    int kk  = k0 + 2 * bk2;
    int tap = kk / CCH;
    int ci  = kk - tap * CCH;
    int dy  = tap / 3 - 1;
    int dx  = tap - (tap / 3) * 3 - 1;
    int yy  = y + dy;
    __half v0[4], v1[4];
    if (yy >= 0 && yy < WID) {
      const __half* s0 = Xb + (size_t)ci * HW + yy * WID;
      const __half* s1 = s0 + HW;
      #pragma unroll
      for (int j = 0; j < 4; j++) {
        int xx = bng + j + dx;
        bool ok = (xx >= 0) & (xx < WID);
        v0[j] = ok ? s0[xx] : hz;
        v1[j] = ok ? s1[xx] : hz;
      }
    } else {
      #pragma unroll
      for (int j = 0; j < 4; j++) { v0[j] = hz; v1[j] = hz; }
    }
    *u = make_uint4(pack_hh(v0[0], v1[0]), pack_hh(v0[1], v1[1]),
                    pack_hh(v0[2], v1[2]), pack_hh(v0[3], v1[3]));
  };

  uint32_t paw[6];
  uint4 pbu;
  #pragma unroll
  for (int i = 0; i < 6; i++) {
    int e = t + i * 256; int k2l = e / 192, m = e - k2l * 192;
    paw[i] = Wp[(size_t)k2l * CCH + m];
  }
  gatherB(0, &pbu);
  #pragma unroll
  for (int i = 0; i < 6; i++) {
    int e = t + i * 256; int k2l = e / 192, m = e - k2l * 192;
    As2[0][k2l][m] = paw[i];
  }
  *(uint4*)&Bs2[0][bk2][bng] = pbu;
  __syncthreads();

  int p = 0;
  for (int k0 = 0; k0 < Ktot; k0 += 16) {
    bool more = (k0 + 16) < Ktot;
    if (more) {
      int k2base = (k0 + 16) >> 1;
      #pragma unroll
      for (int i = 0; i < 6; i++) {
        int e = t + i * 256; int k2l = e / 192, m = e - k2l * 192;
        paw[i] = Wp[(size_t)(k2base + k2l) * CCH + m];
      }
      gatherB(k0 + 16, &pbu);
    }
    {
      uint32_t af[3][4], bf[8][2];
      #pragma unroll
      for (int mt = 0; mt < 3; mt++) {
        int mb = wm * 48 + mt * 16 + grp;
        af[mt][0] = As2[p][t4    ][mb];     af[mt][1] = As2[p][t4    ][mb + 8];
        af[mt][2] = As2[p][t4 + 4][mb];     af[mt][3] = As2[p][t4 + 4][mb + 8];
      }
      #pragma unroll
      for (int nt = 0; nt < 8; nt++) {
        int nb = wn * 64 + nt * 8 + grp;
        bf[nt][0] = Bs2[p][t4][nb]; bf[nt][1] = Bs2[p][t4 + 4][nb];
      }
      #pragma unroll
      for (int mt = 0; mt < 3; mt++)
        #pragma unroll
        for (int nt = 0; nt < 8; nt++)
          mma_fp16(acc[mt][nt], af[mt], bf[nt]);
    }
    if (more) {
      #pragma unroll
      for (int i = 0; i < 6; i++) {
        int e = t + i * 256; int k2l = e / 192, m = e - k2l * 192;
        As2[1-p][k2l][m] = paw[i];
      }
      *(uint4*)&Bs2[1-p][bk2][bng] = pbu;
    }
    __syncthreads();
    p ^= 1;
  }

  const int n0 = y * 128;
  #pragma unroll
  for (int mt = 0; mt < 3; mt++) {
    #pragma unroll
    for (int nt = 0; nt < 8; nt++) {
      int mr = wm * 48 + mt * 16 + grp;
      int nc = n0 + wn * 64 + nt * 8 + t4 * 2;
      *(float2*)&Yb[(size_t)mr * HW + nc] = make_float2(acc[mt][nt][0], acc[mt][nt][1]);
      *(float2*)&Yb[(size_t)(mr + 8) * HW + nc] = make_float2(acc[mt][nt][2], acc[mt][nt][3]);
    }
  }
}

// ------- depthwise 3x3 (groups = 3C), fp16 in / fp32 out, 8 outputs/thread --
__global__ __launch_bounds__(256) void dwconv8_k(
    const __half* __restrict__ in, const float* __restrict__ w,
    float* __restrict__ out)
{
  size_t i8 = (size_t)blockIdx.x * 256 + threadIdx.x;
  size_t base = i8 * 8;
  int s  = (int)(base & (HW - 1));
  size_t bc = base >> 14;
  int c = (int)(bc % C3);
  int y = s >> 7, x0 = s & 127;
  const float* wp = w + (size_t)c * 9;
  const __half* ip = in + (base - s);
  float w0=wp[0],w1=wp[1],w2=wp[2],w3=wp[3],w4=wp[4],w5=wp[5],w6=wp[6],w7=wp[7],w8=wp[8];
  float a[8] = {};
  #pragma unroll
  for (int dy = -1; dy <= 1; dy++) {
    int yy = y + dy;
    if (yy < 0 || yy >= WID) continue;
    const __half* row = ip + yy * WID;
    uint4 u = *(const uint4*)&row[x0];
    const __half2* h2 = (const __half2*)&u;
    float c8[8];
    #pragma unroll
    for (int j = 0; j < 4; j++) {
      float2 f = __half22float2(h2[j]);
      c8[2*j] = f.x; c8[2*j+1] = f.y;
    }
    float lf = (x0 > 0)   ? __half2float(row[x0 - 1]) : 0.f;
    float rt = (x0 < 120) ? __half2float(row[x0 + 8]) : 0.f;
    float r0, r1, r2;
    if (dy < 0)      { r0 = w0; r1 = w1; r2 = w2; }
    else if (dy==0)  { r0 = w3; r1 = w4; r2 = w5; }
    else             { r0 = w6; r1 = w7; r2 = w8; }
    a[0] += r0*lf + r1*c8[0] + r2*c8[1];
    #pragma unroll
    for (int j = 1; j < 7; j++)
      a[j] += r0*c8[j-1] + r1*c8[j] + r2*c8[j+1];
    a[7] += r0*c8[6] + r1*c8[7] + r2*rt;
  }
  *(float4*)&out[base]     = make_float4(a[0], a[1], a[2], a[3]);
  *(float4*)&out[base + 4] = make_float4(a[4], a[5], a[6], a[7]);
}

// ---- logits: raw Grams Gqk = q k^T, Gck = cn k^T + per-channel norm partials
__global__ __launch_bounds__(256) void logits2_k(
    const float* __restrict__ qkv, const float* __restrict__ cnf,
    float* __restrict__ Gqk, float* __restrict__ Gck, float* __restrict__ Np)
{
  int bh = blockIdx.y; int b = bh >> 2, h = bh & 3;
  int chunk = blockIdx.x;
  int s0 = chunk * 1024;
  const float* Q  = qkv + ((size_t)b*C3 + h*CH) * HW;
  const float* Kp = qkv + ((size_t)b*C3 + CCH + h*CH) * HW;
  const float* Cn = cnf + ((size_t)b*CCH + h*CH) * HW;
  __shared__ float Qs[48][68];
  __shared__ float Ks[48][68];
  __shared__ float Cs[48][68];
  const int t = threadIdx.x;
  const int tx = t & 15, ty = t >> 4;
  float aqk[3][3] = {}, ack[3][3] = {};
  float psq[3] = {}, psk[3] = {}, psc[3] = {}, psd[3] = {};
  for (int sc = 0; sc < 1024; sc += 64) {
    #pragma unroll
    for (int i = 0; i < 3; i++) {
      int e = t + i * 256;
      int row = e >> 4;
      int col = (e & 15) * 4;
      float4 q4 = *(const float4*)&Q [(size_t)row*HW + s0 + sc + col];
      float4 c4 = *(const float4*)&Cn[(size_t)row*HW + s0 + sc + col];
      float4 k4 = *(const float4*)&Kp[(size_t)row*HW + s0 + sc + col];
      *(float4*)&Qs[row][col] = q4;
      *(float4*)&Cs[row][col] = c4;
      *(float4*)&Ks[row][col] = k4;
      psq[i] += q4.x*q4.x + q4.y*q4.y + q4.z*q4.z + q4.w*q4.w;
      psk[i] += k4.x*k4.x + k4.y*k4.y + k4.z*k4.z + k4.w*k4.w;
      psc[i] += c4.x*c4.x + c4.y*c4.y + c4.z*c4.z + c4.w*c4.w;
      psd[i] += q4.x*c4.x + q4.y*c4.y + q4.z*c4.z + q4.w*c4.w;
    }
    __syncthreads();
    #pragma unroll 4
    for (int s = 0; s < 64; s++) {
      float qv0 = Qs[ty*3+0][s], qv1 = Qs[ty*3+1][s], qv2 = Qs[ty*3+2][s];
      float cv0 = Cs[ty*3+0][s], cv1 = Cs[ty*3+1][s], cv2 = Cs[ty*3+2][s];
      float kv0 = Ks[tx*3+0][s], kv1 = Ks[tx*3+1][s], kv2 = Ks[tx*3+2][s];
      aqk[0][0]+=qv0*kv0; aqk[0][1]+=qv0*kv1; aqk[0][2]+=qv0*kv2;
      aqk[1][0]+=qv1*kv0; aqk[1][1]+=qv1*kv1; aqk[1][2]+=qv1*kv2;
      aqk[2][0]+=qv2*kv0; aqk[2][1]+=qv2*kv1; aqk[2][2]+=qv2*kv2;
      ack[0][0]+=cv0*kv0; ack[0][1]+=cv0*kv1; ack[0][2]+=cv0*kv2;
      ack[1][0]+=cv1*kv0; ack[1][1]+=cv1*kv1; ack[1][2]+=cv1*kv2;
      ack[2][0]+=cv2*kv0; ack[2][1]+=cv2*kv1; ack[2][2]+=cv2*kv2;
    }
    __syncthreads();
  }
  size_t gbase = ((size_t)chunk * 32 + bh) * CH * CH;
  #pragma unroll
  for (int i = 0; i < 3; i++)
    #pragma unroll
    for (int j = 0; j < 3; j++) {
      Gqk[gbase + (size_t)(ty*3+i)*CH + tx*3+j] = aqk[i][j];
      Gck[gbase + (size_t)(ty*3+i)*CH + tx*3+j] = ack[i][j];
    }
  #pragma unroll
  for (int i = 0; i < 3; i++) {
    int row = (t + i * 256) >> 4;
    float vq = psq[i], vk = psk[i], vc = psc[i], vd = psd[i];
    #pragma unroll
    for (int o = 8; o > 0; o >>= 1) {
      vq += __shfl_down_sync(0xffffffffu, vq, o, 16);
      vk += __shfl_down_sync(0xffffffffu, vk, o, 16);
      vc += __shfl_down_sync(0xffffffffu, vc, o, 16);
      vd += __shfl_down_sync(0xffffffffu, vd, o, 16);
    }
    if ((t & 15) == 0) {
      size_t nb = (((size_t)chunk * 32 + bh) * 4) * CH;
      Np[nb + 0*CH + row] = vq;
      Np[nb + 1*CH + row] = vk;
      Np[nb + 2*CH + row] = vc;
      Np[nb + 3*CH + row] = vd;
    }
  }
}

// ---------------- scalars: reduce norm partials -> alpha, beta, invk --------
__global__ __launch_bounds__(48) void scalars_k(
    const float* __restrict__ Np, float* __restrict__ alpha,
    float* __restrict__ beta, float* __restrict__ invk)
{
  int bh = blockIdx.x; int b = bh >> 2, h = bh & 3;
  int c = threadIdx.x;
  float Sq = 0, Sk = 0, Sc = 0, Sd = 0;
  for (int ch = 0; ch < 16; ch++) {
    size_t nb = (((size_t)ch * 32 + bh) * 4) * CH;
    Sq += Np[nb + 0*CH + c];
    Sk += Np[nb + 1*CH + c];
    Sc += Np[nb + 2*CH + c];
    Sd += Np[nb + 3*CH + c];
  }
  float a  = fmaxf(sqrtf(Sq), EPSV);
  float bb = fmaxf(sqrtf(Sc), EPSV);
  float n2 = Sq/(a*a) + 2.f*Sd/(a*bb) + Sc/(bb*bb);
  float dn = fmaxf(sqrtf(fmaxf(n2, 0.f)), EPSV);
  int bc = b*CCH + h*CH + c;
  alpha[bc] = 1.f / (a * dn);
  beta [bc] = 1.f / (bb * dn);
  invk [bc] = 1.f / fmaxf(sqrtf(Sk), EPSV);
}

// ---------------- softmax over d of t*ik_d*(al_c Gqk + be_c Gck) ------------
__global__ __launch_bounds__(32) void softmax2_k(
    const float* __restrict__ Gqk, const float* __restrict__ Gck,
    const float* __restrict__ alpha, const float* __restrict__ beta,
    const float* __restrict__ invk, const float* __restrict__ temp,
    float* __restrict__ attn)
{
  int row = blockIdx.x;            // bh*48 + c
  int bh = row / CH;
  int c  = row - bh * CH;
  int b  = bh >> 2, h = bh & 3;
  int lane = threadIdx.x;
  float tv = temp[h];
  float al = alpha[b*CCH + h*CH + c];
  float be = beta [b*CCH + h*CH + c];
  bool has1 = (lane + 32) < CH;
  float ik0 = invk[b*CCH + h*CH + lane];
  float ik1 = has1 ? invk[b*CCH + h*CH + lane + 32] : 0.f;
  float gq0 = 0, gc0 = 0, gq1 = 0, gc1 = 0;
  for (int ch = 0; ch < 16; ch++) {
    size_t base = (((size_t)ch*32 + bh)*CH + c)*CH;
    gq0 += Gqk[base + lane]; gc0 += Gck[base + lane];
    if (has1) { gq1 += Gqk[base + lane + 32]; gc1 += Gck[base + lane + 32]; }
  }
  float v0 = (al * gq0 + be * gc0) * ik0 * tv;
  float v1 = (al * gq1 + be * gc1) * ik1 * tv;
  float m = has1 ? fmaxf(v0, v1) : v0;
  #pragma unroll
  for (int o = 16; o > 0; o >>= 1) m = fmaxf(m, __shfl_xor_sync(0xffffffffu, m, o));
  float e0 = __expf(v0 - m);
  float e1 = has1 ? __expf(v1 - m) : 0.f;
  float s = e0 + e1;
  #pragma unroll
  for (int o = 16; o > 0; o >>= 1) s += __shfl_xor_sync(0xffffffffu, s, o);
  float inv = 1.f / s;
  attn[(size_t)row*CH + lane] = e0 * inv;
  if (has1) attn[(size_t)row*CH + lane + 32] = e1 * inv;
}

// ------- M = P @ blockdiag(attn), emitted PRE-PACKED as Mp[k2][192] ---------
__global__ __launch_bounds__(192) void pa_k(
    const float* __restrict__ P, const float* __restrict__ attn,
    uint32_t* __restrict__ Mp)
{
  int bh = blockIdx.x; int b = bh >> 2, h = bh & 3;
  __shared__ float As[48][49];
  const int t = threadIdx.x;
  for (int e = t; e < 48*48; e += 192)
    As[e / 48][e % 48] = attn[(size_t)bh * CH * CH + e];
  __syncthreads();
  float pr[48];
  #pragma unroll
  for (int c = 0; c < 48; c++)
    pr[c] = P[(size_t)t * CCH + h * CH + c];
  float sv[48];
  #pragma unroll 4
  for (int d = 0; d < 48; d++) {
    float s = 0.f;
    #pragma unroll
    for (int c = 0; c < 48; c++) s += pr[c] * As[c][d];
    sv[d] = s;
  }
  #pragma unroll
  for (int j = 0; j < 24; j++)
    Mp[((size_t)b * 96 + h * 24 + j) * CCH + t] = pack_h2(sv[2*j], sv[2*j+1]);
}

// ---------------- launch -----------------------------------------------------
extern "C" void kernel_launch(void* const* d_in, const int* in_sizes, int n_in,
                              void* d_out, int out_size)
{
  const float* x        = (const float*)d_in[0];
  const float* cn       = (const float*)d_in[1];
  const float* cn_w1    = (const float*)d_in[2];
  const float* cn_w3    = (const float*)d_in[3];
  const float* qkv_w    = (const float*)d_in[4];
  const float* qkv_dw_w = (const float*)d_in[5];
  const float* proj_w   = (const float*)d_in[6];
  const float* temp     = (const float*)d_in[7];
  float* out = (float*)d_out;

  __half *cn1, *qkv1;
  uint32_t *Wp3, *Wpq, *Wpc, *Mp;
  float *cnf, *qkv, *al, *be, *ik, *Gqk, *Gck, *Np, *at;
  cudaGetSymbolAddress((void**)&cn1,  g_cn1);
  cudaGetSymbolAddress((void**)&cnf,  g_cnf);
  cudaGetSymbolAddress((void**)&qkv1, g_qkv1);
  cudaGetSymbolAddress((void**)&qkv,  g_qkv);
  cudaGetSymbolAddress((void**)&Wp3,  g_Wp3);
  cudaGetSymbolAddress((void**)&Wpq,  g_Wpq);
  cudaGetSymbolAddress((void**)&Wpc,  g_Wpc);
  cudaGetSymbolAddress((void**)&Mp,   g_Mp);
  cudaGetSymbolAddress((void**)&al,   g_alpha);
  cudaGetSymbolAddress((void**)&be,   g_beta);
  cudaGetSymbolAddress((void**)&ik,   g_invk);
  cudaGetSymbolAddress((void**)&Gqk,  g_Gqk);
  cudaGetSymbolAddress((void**)&Gck,  g_Gck);
  cudaGetSymbolAddress((void**)&Np,   g_Np);
  cudaGetSymbolAddress((void**)&at,   g_attn);

  // weight transforms (tiny, independent)
  wtrans1_k<<<(96*CCH + 255)/256, 256>>>(cn_w1, Wpc, CCH);
  wtrans1_k<<<(96*C3  + 255)/256, 256>>>(qkv_w, Wpq, C3);
  wtrans3_k<<<((CCH*9/2)*CCH + 255)/256, 256>>>(cn_w3, Wp3);

  dim3 g1(HW/128, 1, NB);
  gemm1x1p_fp16<__half><<<g1, 256>>>(Wpc, cn, cn1, CCH,
                                     0, (size_t)CCH*HW, (size_t)CCH*HW);
  conv3x3_fp16<<<g1, 256>>>(Wp3, cn1, cnf);

  dim3 g2(HW/128, 3, NB);
  gemm1x1p_fp16<__half><<<g2, 256>>>(Wpq, x, qkv1, C3,
                                     0, (size_t)CCH*HW, (size_t)C3*HW);

  size_t ndw8 = (size_t)NB * C3 * HW / 8;
  dwconv8_k<<<(unsigned)(ndw8 / 256), 256>>>(qkv1, qkv_dw_w, qkv);

  logits2_k<<<dim3(16, NB*NHEAD), 256>>>(qkv, cnf, Gqk, Gck, Np);
  scalars_k<<<NB*NHEAD, 48>>>(Np, al, be, ik);
  softmax2_k<<<NB*NHEAD*CH, 32>>>(Gqk, Gck, al, be, ik, temp, at);
  pa_k<<<NB*NHEAD, 192>>>(proj_w, at, Mp);

  // fused (attn@v + proj): out_b = Mp_b @ v_b
  gemm1x1p_fp16<float><<<g1, 256>>>(Mp, qkv + (size_t)2*CCH*HW, out, CCH,
                                    (size_t)96*CCH, (size_t)C3*HW, (size_t)CCH*HW);
}

// round 13
// speedup vs baseline: 1.4336x; 1.4336x over previous
#include <cuda_runtime.h>
#include <cuda_fp16.h>
#include <math.h>
#include <stdint.h>

#define HW    16384
#define WID   128
#define CCH   192
#define C3    576
#define NB    8
#define NHEAD 4
#define CH    48
#define EPSV  1e-12f

// ---------------- scratch (device globals; allocation-free) ----------------
__device__ __align__(16) __half g_cn1 [(size_t)NB*CCH*HW];
__device__ __align__(16) float  g_cnf [(size_t)NB*CCH*HW];
__device__ __align__(16) __half g_qkv1[(size_t)NB*C3 *HW];
__device__ __align__(16) float  g_qkv [(size_t)NB*C3 *HW];
__device__ __align__(16) uint32_t g_Wp3[(size_t)(CCH*9/2)*CCH];
__device__ float g_alpha[NB*CCH];
__device__ float g_beta [NB*CCH];
__device__ float g_invk [NB*CCH];
__device__ float g_Gqk [(size_t)16*32*CH*CH];
__device__ float g_Gck [(size_t)16*32*CH*CH];
__device__ float g_Np  [(size_t)16*32*4*CH];
__device__ float g_attn[(size_t)NB*NHEAD*CH*CH];
__device__ float g_M   [(size_t)NB*CCH*CCH];

__device__ __forceinline__ uint32_t pack_h2(float lo, float hi) {
  __half2 h = __floats2half2_rn(lo, hi);
  return *(uint32_t*)&h;
}
__device__ __forceinline__ uint32_t pack_hh(__half lo, __half hi) {
  __half2 h = __halves2half2(lo, hi);
  return *(uint32_t*)&h;
}
__device__ __forceinline__ void store2(float* p, float a, float b) {
  *(float2*)p = make_float2(a, b);
}
__device__ __forceinline__ void store2(__half* p, float a, float b) {
  *(uint32_t*)p = pack_h2(a, b);
}
__device__ __forceinline__ void mma_fp16(float* c, const uint32_t* a, const uint32_t* b) {
  asm volatile(
    "mma.sync.aligned.m16n8k16.row.col.f32.f16.f16.f32 "
    "{%0,%1,%2,%3},{%4,%5,%6,%7},{%8,%9},{%0,%1,%2,%3};"
    : "+f"(c[0]), "+f"(c[1]), "+f"(c[2]), "+f"(c[3])
    : "r"(a[0]), "r"(a[1]), "r"(a[2]), "r"(a[3]), "r"(b[0]), "r"(b[1]));
}

#define AST 200
#define BST 136

// ======= fused front GEMM: slab 0 = cn1x1, slabs 1..3 = qkv1x1 (K=192) ======
// Identical body to the proven R9 gemm; only the pointer selection differs.
__global__ __launch_bounds__(256, 1) void gemm_front_fp16(
    const float* __restrict__ cn_w1, const float* __restrict__ qkv_w,
    const float* __restrict__ cn_in, const float* __restrict__ x_in,
    __half* __restrict__ cn1, __half* __restrict__ qkv1)
{
  const int b    = blockIdx.z;
  const int slab = blockIdx.y;
  const int n0   = blockIdx.x * 128;
  const int K    = CCH;

  const float* Wb;
  const float* Xb;
  __half* Yb;
  int m0;
  if (slab == 0) {
    Wb = cn_w1; Xb = cn_in + (size_t)b * CCH * HW;
    Yb = cn1 + (size_t)b * CCH * HW; m0 = 0;
  } else {
    Wb = qkv_w; Xb = x_in + (size_t)b * CCH * HW;
    Yb = qkv1 + (size_t)b * C3 * HW; m0 = (slab - 1) * 192;
  }

  __shared__ uint32_t As2[2][8][AST];
  __shared__ uint32_t Bs2[2][8][BST];

  const int t    = threadIdx.x;
  const int wid  = t >> 5, lane = t & 31;
  const int wm   = wid >> 1, wn = wid & 1;
  const int grp  = lane >> 2, t4 = lane & 3;

  float acc[3][8][4] = {};

  const int bk2 = t >> 5;
  const int bng = (t & 31) * 4;

  float4 pa[3], pb0, pb1;
  #pragma unroll
  for (int i = 0; i < 3; i++) {
    int e = t + i * 256; int row = e >> 2, kf = (e & 3) * 4;
    pa[i] = *(const float4*)&Wb[(size_t)(m0 + row) * K + kf];
  }
  pb0 = *(const float4*)&Xb[(size_t)(2 * bk2    ) * HW + n0 + bng];
  pb1 = *(const float4*)&Xb[(size_t)(2 * bk2 + 1) * HW + n0 + bng];
  #pragma unroll
  for (int i = 0; i < 3; i++) {
    int e = t + i * 256; int row = e >> 2, k2 = (e & 3) * 2;
    As2[0][k2  ][row] = pack_h2(pa[i].x, pa[i].y);
    As2[0][k2+1][row] = pack_h2(pa[i].z, pa[i].w);
  }
  {
    uint4 u = make_uint4(pack_h2(pb0.x, pb1.x), pack_h2(pb0.y, pb1.y),
                         pack_h2(pb0.z, pb1.z), pack_h2(pb0.w, pb1.w));
    *(uint4*)&Bs2[0][bk2][bng] = u;
  }
  __syncthreads();

  int p = 0;
  for (int k0 = 0; k0 < K; k0 += 16) {
    bool more = (k0 + 16) < K;
    if (more) {
      #pragma unroll
      for (int i = 0; i < 3; i++) {
        int e = t + i * 256; int row = e >> 2, kf = (e & 3) * 4;
        pa[i] = *(const float4*)&Wb[(size_t)(m0 + row) * K + k0 + 16 + kf];
      }
      pb0 = *(const float4*)&Xb[(size_t)(k0 + 16 + 2 * bk2    ) * HW + n0 + bng];
      pb1 = *(const float4*)&Xb[(size_t)(k0 + 16 + 2 * bk2 + 1) * HW + n0 + bng];
    }
    {
      uint32_t af[3][4], bf[8][2];
      #pragma unroll
      for (int mt = 0; mt < 3; mt++) {
        int mb = wm * 48 + mt * 16 + grp;
        af[mt][0] = As2[p][t4    ][mb];     af[mt][1] = As2[p][t4    ][mb + 8];
        af[mt][2] = As2[p][t4 + 4][mb];     af[mt][3] = As2[p][t4 + 4][mb + 8];
      }
      #pragma unroll
      for (int nt = 0; nt < 8; nt++) {
        int nb = wn * 64 + nt * 8 + grp;
        bf[nt][0] = Bs2[p][t4][nb]; bf[nt][1] = Bs2[p][t4 + 4][nb];
      }
      #pragma unroll
      for (int mt = 0; mt < 3; mt++)
        #pragma unroll
        for (int nt = 0; nt < 8; nt++)
          mma_fp16(acc[mt][nt], af[mt], bf[nt]);
    }
    if (more) {
      #pragma unroll
      for (int i = 0; i < 3; i++) {
        int e = t + i * 256; int row = e >> 2, k2 = (e & 3) * 2;
        As2[1-p][k2  ][row] = pack_h2(pa[i].x, pa[i].y);
        As2[1-p][k2+1][row] = pack_h2(pa[i].z, pa[i].w);
      }
      uint4 u = make_uint4(pack_h2(pb0.x, pb1.x), pack_h2(pb0.y, pb1.y),
                           pack_h2(pb0.z, pb1.z), pack_h2(pb0.w, pb1.w));
      *(uint4*)&Bs2[1-p][bk2][bng] = u;
    }
    __syncthreads();
    p ^= 1;
  }

  #pragma unroll
  for (int mt = 0; mt < 3; mt++) {
    #pragma unroll
    for (int nt = 0; nt < 8; nt++) {
      int mr = m0 + wm * 48 + mt * 16 + grp;
      int nc = n0 + wn * 64 + nt * 8 + t4 * 2;
      store2(&Yb[(size_t)mr * HW + nc], acc[mt][nt][0], acc[mt][nt][1]);
      store2(&Yb[(size_t)(mr + 8) * HW + nc], acc[mt][nt][2], acc[mt][nt][3]);
    }
  }
}

// ================ fp16 tensor-core GEMM (R9 proven; used for Mv) ============
template <typename OutT>
__global__ __launch_bounds__(256, 1) void gemm1x1_fp16(
    const float* __restrict__ Wm, const float* __restrict__ X,
    OutT* __restrict__ Y, int K,
    size_t wstride, size_t xstride, size_t ystride)
{
  const int b  = blockIdx.z;
  const int m0 = blockIdx.y * 192;
  const int n0 = blockIdx.x * 128;
  const float* Wb = Wm + (size_t)b * wstride;
  const float* Xb = X + (size_t)b * xstride;
  OutT* Yb = Y + (size_t)b * ystride;

  __shared__ uint32_t As2[2][8][AST];
  __shared__ uint32_t Bs2[2][8][BST];

  const int t    = threadIdx.x;
  const int wid  = t >> 5, lane = t & 31;
  const int wm   = wid >> 1, wn = wid & 1;
  const int grp  = lane >> 2, t4 = lane & 3;

  float acc[3][8][4] = {};

  const int bk2 = t >> 5;
  const int bng = (t & 31) * 4;

  float4 pa[3], pb0, pb1;
  #pragma unroll
  for (int i = 0; i < 3; i++) {
    int e = t + i * 256; int row = e >> 2, kf = (e & 3) * 4;
    pa[i] = *(const float4*)&Wb[(size_t)(m0 + row) * K + kf];
  }
  pb0 = *(const float4*)&Xb[(size_t)(2 * bk2    ) * HW + n0 + bng];
  pb1 = *(const float4*)&Xb[(size_t)(2 * bk2 + 1) * HW + n0 + bng];
  #pragma unroll
  for (int i = 0; i < 3; i++) {
    int e = t + i * 256; int row = e >> 2, k2 = (e & 3) * 2;
    As2[0][k2  ][row] = pack_h2(pa[i].x, pa[i].y);
    As2[0][k2+1][row] = pack_h2(pa[i].z, pa[i].w);
  }
  {
    uint4 u = make_uint4(pack_h2(pb0.x, pb1.x), pack_h2(pb0.y, pb1.y),
                         pack_h2(pb0.z, pb1.z), pack_h2(pb0.w, pb1.w));
    *(uint4*)&Bs2[0][bk2][bng] = u;
  }
  __syncthreads();

  int p = 0;
  for (int k0 = 0; k0 < K; k0 += 16) {
    bool more = (k0 + 16) < K;
    if (more) {
      #pragma unroll
      for (int i = 0; i < 3; i++) {
        int e = t + i * 256; int row = e >> 2, kf = (e & 3) * 4;
        pa[i] = *(const float4*)&Wb[(size_t)(m0 + row) * K + k0 + 16 + kf];
      }
      pb0 = *(const float4*)&Xb[(size_t)(k0 + 16 + 2 * bk2    ) * HW + n0 + bng];
      pb1 = *(const float4*)&Xb[(size_t)(k0 + 16 + 2 * bk2 + 1) * HW + n0 + bng];
    }
    {
      uint32_t af[3][4], bf[8][2];
      #pragma unroll
      for (int mt = 0; mt < 3; mt++) {
        int mb = wm * 48 + mt * 16 + grp;
        af[mt][0] = As2[p][t4    ][mb];     af[mt][1] = As2[p][t4    ][mb + 8];
        af[mt][2] = As2[p][t4 + 4][mb];     af[mt][3] = As2[p][t4 + 4][mb + 8];
      }
      #pragma unroll
      for (int nt = 0; nt < 8; nt++) {
        int nb = wn * 64 + nt * 8 + grp;
        bf[nt][0] = Bs2[p][t4][nb]; bf[nt][1] = Bs2[p][t4 + 4][nb];
      }
      #pragma unroll
      for (int mt = 0; mt < 3; mt++)
        #pragma unroll
        for (int nt = 0; nt < 8; nt++)
          mma_fp16(acc[mt][nt], af[mt], bf[nt]);
    }
    if (more) {
      #pragma unroll
      for (int i = 0; i < 3; i++) {
        int e = t + i * 256; int row = e >> 2, k2 = (e & 3) * 2;
        As2[1-p][k2  ][row] = pack_h2(pa[i].x, pa[i].y);
        As2[1-p][k2+1][row] = pack_h2(pa[i].z, pa[i].w);
      }
      uint4 u = make_uint4(pack_h2(pb0.x, pb1.x), pack_h2(pb0.y, pb1.y),
                           pack_h2(pb0.z, pb1.z), pack_h2(pb0.w, pb1.w));
      *(uint4*)&Bs2[1-p][bk2][bng] = u;
    }
    __syncthreads();
    p ^= 1;
  }

  #pragma unroll
  for (int mt = 0; mt < 3; mt++) {
    #pragma unroll
    for (int nt = 0; nt < 8; nt++) {
      int mr = m0 + wm * 48 + mt * 16 + grp;
      int nc = n0 + wn * 64 + nt * 8 + t4 * 2;
      store2(&Yb[(size_t)mr * HW + nc], acc[mt][nt][0], acc[mt][nt][1]);
      store2(&Yb[(size_t)(mr + 8) * HW + nc], acc[mt][nt][2], acc[mt][nt][3]);
    }
  }
}

// ------- conv3 weight transform: W[m][ci*9+tap] -> packed Wp[k2][m] ---------
__global__ __launch_bounds__(256) void wtrans3_k(
    const float* __restrict__ W, uint32_t* __restrict__ Wp)
{
  int e = blockIdx.x * 256 + threadIdx.x;
  if (e >= (CCH*9/2) * CCH) return;
  int k2 = e / CCH, m = e - k2 * CCH;
  int k  = k2 * 2;
  int tap = k / CCH;
  int ci  = k - tap * CCH;
  float a = W[(size_t)m * (CCH*9) + ci * 9 + tap];
  float b = W[(size_t)m * (CCH*9) + (ci + 1) * 9 + tap];
  Wp[(size_t)k2 * CCH + m] = pack_h2(a, b);
}

// ====== fp16 conv3x3, reordered-K implicit GEMM, prepacked weights (R9) =====
__global__ __launch_bounds__(256, 1) void conv3x3_fp16(
    const uint32_t* __restrict__ Wp, const __half* __restrict__ X,
    float* __restrict__ Y)
{
  const int Ktot = CCH * 9;
  const int b = blockIdx.z;
  const int y = blockIdx.x;
  const __half* Xb = X + (size_t)b * CCH * HW;
  float* Yb = Y + (size_t)b * CCH * HW;

  __shared__ uint32_t As2[2][8][AST];
  __shared__ uint32_t Bs2[2][8][BST];

  const int t   = threadIdx.x;
  const int wid = t >> 5, lane = t & 31;
  const int wm  = wid >> 1, wn = wid & 1;
  const int grp = lane >> 2, t4 = lane & 3;

  float acc[3][8][4] = {};

  const int bk2 = t >> 5;
  const int bng = (t & 31) * 4;

  const __half hz = __float2half(0.f);

  auto gatherB = [&](int k0, uint4* u) {
    int kk  = k0 + 2 * bk2;
    int tap = kk / CCH;
    int ci  = kk - tap * CCH;
    int dy  = tap / 3 - 1;
    int dx  = tap - (tap / 3) * 3 - 1;
    int yy  = y + dy;
    __half v0[4], v1[4];
    if (yy >= 0 && yy < WID) {
      const __half* s0 = Xb + (size_t)ci * HW + yy * WID;
      const __half* s1 = s0 + HW;
      #pragma unroll
      for (int j = 0; j < 4; j++) {
        int xx = bng + j + dx;
        bool ok = (xx >= 0) & (xx < WID);
        v0[j] = ok ? s0[xx] : hz;
        v1[j] = ok ? s1[xx] : hz;
      }
    } else {
      #pragma unroll
      for (int j = 0; j < 4; j++) { v0[j] = hz; v1[j] = hz; }
    }
    *u = make_uint4(pack_hh(v0[0], v1[0]), pack_hh(v0[1], v1[1]),
                    pack_hh(v0[2], v1[2]), pack_hh(v0[3], v1[3]));
  };

  uint32_t paw[6];
  uint4 pbu;
  #pragma unroll
  for (int i = 0; i < 6; i++) {
    int e = t + i * 256; int k2l = e / 192, m = e - k2l * 192;
    paw[i] = Wp[(size_t)k2l * CCH + m];
  }
  gatherB(0, &pbu);
  #pragma unroll
  for (int i = 0; i < 6; i++) {
    int e = t + i * 256; int k2l = e / 192, m = e - k2l * 192;
    As2[0][k2l][m] = paw[i];
  }
  *(uint4*)&Bs2[0][bk2][bng] = pbu;
  __syncthreads();

  int p = 0;
  for (int k0 = 0; k0 < Ktot; k0 += 16) {
    bool more = (k0 + 16) < Ktot;
    if (more) {
      int k2base = (k0 + 16) >> 1;
      #pragma unroll
      for (int i = 0; i < 6; i++) {
        int e = t + i * 256; int k2l = e / 192, m = e - k2l * 192;
        paw[i] = Wp[(size_t)(k2base + k2l) * CCH + m];
      }
      gatherB(k0 + 16, &pbu);
    }
    {
      uint32_t af[3][4], bf[8][2];
      #pragma unroll
      for (int mt = 0; mt < 3; mt++) {
        int mb = wm * 48 + mt * 16 + grp;
        af[mt][0] = As2[p][t4    ][mb];     af[mt][1] = As2[p][t4    ][mb + 8];
        af[mt][2] = As2[p][t4 + 4][mb];     af[mt][3] = As2[p][t4 + 4][mb + 8];
      }
      #pragma unroll
      for (int nt = 0; nt < 8; nt++) {
        int nb = wn * 64 + nt * 8 + grp;
        bf[nt][0] = Bs2[p][t4][nb]; bf[nt][1] = Bs2[p][t4 + 4][nb];
      }
      #pragma unroll
      for (int mt = 0; mt < 3; mt++)
        #pragma unroll
        for (int nt = 0; nt < 8; nt++)
          mma_fp16(acc[mt][nt], af[mt], bf[nt]);
    }
    if (more) {
      #pragma unroll
      for (int i = 0; i < 6; i++) {
        int e = t + i * 256; int k2l = e / 192, m = e - k2l * 192;
        As2[1-p][k2l][m] = paw[i];
      }
      *(uint4*)&Bs2[1-p][bk2][bng] = pbu;
    }
    __syncthreads();
    p ^= 1;
  }

  const int n0 = y * 128;
  #pragma unroll
  for (int mt = 0; mt < 3; mt++) {
    #pragma unroll
    for (int nt = 0; nt < 8; nt++) {
      int mr = wm * 48 + mt * 16 + grp;
      int nc = n0 + wn * 64 + nt * 8 + t4 * 2;
      *(float2*)&Yb[(size_t)mr * HW + nc] = make_float2(acc[mt][nt][0], acc[mt][nt][1]);
      *(float2*)&Yb[(size_t)(mr + 8) * HW + nc] = make_float2(acc[mt][nt][2], acc[mt][nt][3]);
    }
  }
}

// ------- depthwise 3x3 (groups = 3C), fp16 in / fp32 out, 8 outputs/thread --
__global__ __launch_bounds__(256) void dwconv8_k(
    const __half* __restrict__ in, const float* __restrict__ w,
    float* __restrict__ out)
{
  size_t i8 = (size_t)blockIdx.x * 256 + threadIdx.x;
  size_t base = i8 * 8;
  int s  = (int)(base & (HW - 1));
  size_t bc = base >> 14;
  int c = (int)(bc % C3);
  int y = s >> 7, x0 = s & 127;
  const float* wp = w + (size_t)c * 9;
  const __half* ip = in + (base - s);
  float w0=wp[0],w1=wp[1],w2=wp[2],w3=wp[3],w4=wp[4],w5=wp[5],w6=wp[6],w7=wp[7],w8=wp[8];
  float a[8] = {};
  #pragma unroll
  for (int dy = -1; dy <= 1; dy++) {
    int yy = y + dy;
    if (yy < 0 || yy >= WID) continue;
    const __half* row = ip + yy * WID;
    uint4 u = *(const uint4*)&row[x0];
    const __half2* h2 = (const __half2*)&u;
    float c8[8];
    #pragma unroll
    for (int j = 0; j < 4; j++) {
      float2 f = __half22float2(h2[j]);
      c8[2*j] = f.x; c8[2*j+1] = f.y;
    }
    float lf = (x0 > 0)   ? __half2float(row[x0 - 1]) : 0.f;
    float rt = (x0 < 120) ? __half2float(row[x0 + 8]) : 0.f;
    float r0, r1, r2;
    if (dy < 0)      { r0 = w0; r1 = w1; r2 = w2; }
    else if (dy==0)  { r0 = w3; r1 = w4; r2 = w5; }
    else             { r0 = w6; r1 = w7; r2 = w8; }
    a[0] += r0*lf + r1*c8[0] + r2*c8[1];
    #pragma unroll
    for (int j = 1; j < 7; j++)
      a[j] += r0*c8[j-1] + r1*c8[j] + r2*c8[j+1];
    a[7] += r0*c8[6] + r1*c8[7] + r2*rt;
  }
  *(float4*)&out[base]     = make_float4(a[0], a[1], a[2], a[3]);
  *(float4*)&out[base + 4] = make_float4(a[4], a[5], a[6], a[7]);
}

// ---- logits: raw Grams Gqk = q k^T, Gck = cn k^T + per-channel norm partials
__global__ __launch_bounds__(256) void logits2_k(
    const float* __restrict__ qkv, const float* __restrict__ cnf,
    float* __restrict__ Gqk, float* __restrict__ Gck, float* __restrict__ Np)
{
  int bh = blockIdx.y; int b = bh >> 2, h = bh & 3;
  int chunk = blockIdx.x;
  int s0 = chunk * 1024;
  const float* Q  = qkv + ((size_t)b*C3 + h*CH) * HW;
  const float* Kp = qkv + ((size_t)b*C3 + CCH + h*CH) * HW;
  const float* Cn = cnf + ((size_t)b*CCH + h*CH) * HW;
  __shared__ float Qs[48][68];
  __shared__ float Ks[48][68];
  __shared__ float Cs[48][68];
  const int t = threadIdx.x;
  const int tx = t & 15, ty = t >> 4;
  float aqk[3][3] = {}, ack[3][3] = {};
  float psq[3] = {}, psk[3] = {}, psc[3] = {}, psd[3] = {};
  for (int sc = 0; sc < 1024; sc += 64) {
    #pragma unroll
    for (int i = 0; i < 3; i++) {
      int e = t + i * 256;
      int row = e >> 4;
      int col = (e & 15) * 4;
      float4 q4 = *(const float4*)&Q [(size_t)row*HW + s0 + sc + col];
      float4 c4 = *(const float4*)&Cn[(size_t)row*HW + s0 + sc + col];
      float4 k4 = *(const float4*)&Kp[(size_t)row*HW + s0 + sc + col];
      *(float4*)&Qs[row][col] = q4;
      *(float4*)&Cs[row][col] = c4;
      *(float4*)&Ks[row][col] = k4;
      psq[i] += q4.x*q4.x + q4.y*q4.y + q4.z*q4.z + q4.w*q4.w;
      psk[i] += k4.x*k4.x + k4.y*k4.y + k4.z*k4.z + k4.w*k4.w;
      psc[i] += c4.x*c4.x + c4.y*c4.y + c4.z*c4.z + c4.w*c4.w;
      psd[i] += q4.x*c4.x + q4.y*c4.y + q4.z*c4.z + q4.w*c4.w;
    }
    __syncthreads();
    #pragma unroll 4
    for (int s = 0; s < 64; s++) {
      float qv0 = Qs[ty*3+0][s], qv1 = Qs[ty*3+1][s], qv2 = Qs[ty*3+2][s];
      float cv0 = Cs[ty*3+0][s], cv1 = Cs[ty*3+1][s], cv2 = Cs[ty*3+2][s];
      float kv0 = Ks[tx*3+0][s], kv1 = Ks[tx*3+1][s], kv2 = Ks[tx*3+2][s];
      aqk[0][0]+=qv0*kv0; aqk[0][1]+=qv0*kv1; aqk[0][2]+=qv0*kv2;
      aqk[1][0]+=qv1*kv0; aqk[1][1]+=qv1*kv1; aqk[1][2]+=qv1*kv2;
      aqk[2][0]+=qv2*kv0; aqk[2][1]+=qv2*kv1; aqk[2][2]+=qv2*kv2;
      ack[0][0]+=cv0*kv0; ack[0][1]+=cv0*kv1; ack[0][2]+=cv0*kv2;
      ack[1][0]+=cv1*kv0; ack[1][1]+=cv1*kv1; ack[1][2]+=cv1*kv2;
      ack[2][0]+=cv2*kv0; ack[2][1]+=cv2*kv1; ack[2][2]+=cv2*kv2;
    }
    __syncthreads();
  }
  size_t gbase = ((size_t)chunk * 32 + bh) * CH * CH;
  #pragma unroll
  for (int i = 0; i < 3; i++)
    #pragma unroll
    for (int j = 0; j < 3; j++) {
      Gqk[gbase + (size_t)(ty*3+i)*CH + tx*3+j] = aqk[i][j];
      Gck[gbase + (size_t)(ty*3+i)*CH + tx*3+j] = ack[i][j];
    }
  #pragma unroll
  for (int i = 0; i < 3; i++) {
    int row = (t + i * 256) >> 4;
    float vq = psq[i], vk = psk[i], vc = psc[i], vd = psd[i];
    #pragma unroll
    for (int o = 8; o > 0; o >>= 1) {
      vq += __shfl_down_sync(0xffffffffu, vq, o, 16);
      vk += __shfl_down_sync(0xffffffffu, vk, o, 16);
      vc += __shfl_down_sync(0xffffffffu, vc, o, 16);
      vd += __shfl_down_sync(0xffffffffu, vd, o, 16);
    }
    if ((t & 15) == 0) {
      size_t nb = (((size_t)chunk * 32 + bh) * 4) * CH;
      Np[nb + 0*CH + row] = vq;
      Np[nb + 1*CH + row] = vk;
      Np[nb + 2*CH + row] = vc;
      Np[nb + 3*CH + row] = vd;
    }
  }
}

// ---------------- scalars: reduce norm partials -> alpha, beta, invk --------
__global__ __launch_bounds__(48) void scalars_k(
    const float* __restrict__ Np, float* __restrict__ alpha,
    float* __restrict__ beta, float* __restrict__ invk)
{
  int bh = blockIdx.x; int b = bh >> 2, h = bh & 3;
  int c = threadIdx.x;
  float Sq = 0, Sk = 0, Sc = 0, Sd = 0;
  for (int ch = 0; ch < 16; ch++) {
    size_t nb = (((size_t)ch * 32 + bh) * 4) * CH;
    Sq += Np[nb + 0*CH + c];
    Sk += Np[nb + 1*CH + c];
    Sc += Np[nb + 2*CH + c];
    Sd += Np[nb + 3*CH + c];
  }
  float a  = fmaxf(sqrtf(Sq), EPSV);
  float bb = fmaxf(sqrtf(Sc), EPSV);
  float n2 = Sq/(a*a) + 2.f*Sd/(a*bb) + Sc/(bb*bb);
  float dn = fmaxf(sqrtf(fmaxf(n2, 0.f)), EPSV);
  int bc = b*CCH + h*CH + c;
  alpha[bc] = 1.f / (a * dn);
  beta [bc] = 1.f / (bb * dn);
  invk [bc] = 1.f / fmaxf(sqrtf(Sk), EPSV);
}

// ---------------- softmax over d of t*ik_d*(al_c Gqk + be_c Gck) ------------
__global__ __launch_bounds__(32) void softmax2_k(
    const float* __restrict__ Gqk, const float* __restrict__ Gck,
    const float* __restrict__ alpha, const float* __restrict__ beta,
    const float* __restrict__ invk, const float* __restrict__ temp,
    float* __restrict__ attn)
{
  int row = blockIdx.x;            // bh*48 + c
  int bh = row / CH;
  int c  = row - bh * CH;
  int b  = bh >> 2, h = bh & 3;
  int lane = threadIdx.x;
  float tv = temp[h];
  float al = alpha[b*CCH + h*CH + c];
  float be = beta [b*CCH + h*CH + c];
  bool has1 = (lane + 32) < CH;
  float ik0 = invk[b*CCH + h*CH + lane];
  float ik1 = has1 ? invk[b*CCH + h*CH + lane + 32] : 0.f;
  float gq0 = 0, gc0 = 0, gq1 = 0, gc1 = 0;
  for (int ch = 0; ch < 16; ch++) {
    size_t base = (((size_t)ch*32 + bh)*CH + c)*CH;
    gq0 += Gqk[base + lane]; gc0 += Gck[base + lane];
    if (has1) { gq1 += Gqk[base + lane + 32]; gc1 += Gck[base + lane + 32]; }
  }
  float v0 = (al * gq0 + be * gc0) * ik0 * tv;
  float v1 = (al * gq1 + be * gc1) * ik1 * tv;
  float m = has1 ? fmaxf(v0, v1) : v0;
  #pragma unroll
  for (int o = 16; o > 0; o >>= 1) m = fmaxf(m, __shfl_xor_sync(0xffffffffu, m, o));
  float e0 = __expf(v0 - m);
  float e1 = has1 ? __expf(v1 - m) : 0.f;
  float s = e0 + e1;
  #pragma unroll
  for (int o = 16; o > 0; o >>= 1) s += __shfl_xor_sync(0xffffffffu, s, o);
  float inv = 1.f / s;
  attn[(size_t)row*CH + lane] = e0 * inv;
  if (has1) attn[(size_t)row*CH + lane + 32] = e1 * inv;
}

// ---------------- M = P @ blockdiag(attn): per-batch fused proj weights ----
__global__ __launch_bounds__(192) void pa_k(
    const float* __restrict__ P, const float* __restrict__ attn,
    float* __restrict__ M)
{
  int bh = blockIdx.x; int b = bh >> 2, h = bh & 3;
  __shared__ float As[48][49];
  const int t = threadIdx.x;
  for (int e = t; e < 48*48; e += 192)
    As[e / 48][e % 48] = attn[(size_t)bh * CH * CH + e];
  __syncthreads();
  float pr[48];
  #pragma unroll
  for (int c = 0; c < 48; c++)
    pr[c] = P[(size_t)t * CCH + h * CH + c];
  #pragma unroll 4
  for (int d = 0; d < 48; d++) {
    float s = 0.f;
    #pragma unroll
    for (int c = 0; c < 48; c++) s += pr[c] * As[c][d];
    M[((size_t)b * CCH + t) * CCH + h * CH + d] = s;
  }
}

// ---------------- launch -----------------------------------------------------
extern "C" void kernel_launch(void* const* d_in, const int* in_sizes, int n_in,
                              void* d_out, int out_size)
{
  const float* x        = (const float*)d_in[0];
  const float* cn       = (const float*)d_in[1];
  const float* cn_w1    = (const float*)d_in[2];
  const float* cn_w3    = (const float*)d_in[3];
  const float* qkv_w    = (const float*)d_in[4];
  const float* qkv_dw_w = (const float*)d_in[5];
  const float* proj_w   = (const float*)d_in[6];
  const float* temp     = (const float*)d_in[7];
  float* out = (float*)d_out;

  __half *cn1, *qkv1;
  uint32_t *Wp3;
  float *cnf, *qkv, *al, *be, *ik, *Gqk, *Gck, *Np, *at, *Mw;
  cudaGetSymbolAddress((void**)&cn1,  g_cn1);
  cudaGetSymbolAddress((void**)&cnf,  g_cnf);
  cudaGetSymbolAddress((void**)&qkv1, g_qkv1);
  cudaGetSymbolAddress((void**)&qkv,  g_qkv);
  cudaGetSymbolAddress((void**)&Wp3,  g_Wp3);
  cudaGetSymbolAddress((void**)&al,   g_alpha);
  cudaGetSymbolAddress((void**)&be,   g_beta);
  cudaGetSymbolAddress((void**)&ik,   g_invk);
  cudaGetSymbolAddress((void**)&Gqk,  g_Gqk);
  cudaGetSymbolAddress((void**)&Gck,  g_Gck);
  cudaGetSymbolAddress((void**)&Np,   g_Np);
  cudaGetSymbolAddress((void**)&at,   g_attn);
  cudaGetSymbolAddress((void**)&Mw,   g_M);

  // conv3 weight transform (independent; runs ahead)
  wtrans3_k<<<((CCH*9/2)*CCH + 255)/256, 256>>>(cn_w3, Wp3);

  // fused front GEMMs: slab 0 = cn1x1 -> cn1, slabs 1..3 = qkv1x1 -> qkv1
  gemm_front_fp16<<<dim3(HW/128, 4, NB), 256>>>(cn_w1, qkv_w, cn, x, cn1, qkv1);

  conv3x3_fp16<<<dim3(HW/128, 1, NB), 256>>>(Wp3, cn1, cnf);

  size_t ndw8 = (size_t)NB * C3 * HW / 8;
  dwconv8_k<<<(unsigned)(ndw8 / 256), 256>>>(qkv1, qkv_dw_w, qkv);

  logits2_k<<<dim3(16, NB*NHEAD), 256>>>(qkv, cnf, Gqk, Gck, Np);
  scalars_k<<<NB*NHEAD, 48>>>(Np, al, be, ik);
  softmax2_k<<<NB*NHEAD*CH, 32>>>(Gqk, Gck, al, be, ik, temp, at);
  pa_k<<<NB*NHEAD, 192>>>(proj_w, at, Mw);

  // fused (attn@v + proj): out_b = M_b @ v_b
  gemm1x1_fp16<float><<<dim3(HW/128, 1, NB), 256>>>(
      Mw, qkv + (size_t)2*CCH*HW, out, CCH,
      (size_t)CCH*CCH, (size_t)C3*HW, (size_t)CCH*HW);
}

// round 16
// speedup vs baseline: 1.4662x; 1.0227x over previous
#include <cuda_runtime.h>
#include <cuda_fp16.h>
#include <math.h>
#include <stdint.h>

#define HW    16384
#define WID   128
#define CCH   192
#define C3    576
#define NB    8
#define NHEAD 4
#define CH    48
#define EPSV  1e-12f

// ---------------- scratch (device globals; allocation-free) ----------------
__device__ __align__(16) __half g_cn1 [(size_t)NB*CCH*HW];
__device__ __align__(16) float  g_cnf [(size_t)NB*CCH*HW];
__device__ __align__(16) __half g_qkv1[(size_t)NB*C3 *HW];
__device__ __align__(16) float  g_qkv [(size_t)NB*C3 *HW];
__device__ __align__(16) uint32_t g_Wp3[(size_t)(CCH*9/2)*CCH];
__device__ float g_Gqk [(size_t)16*32*CH*CH];
__device__ float g_Gck [(size_t)16*32*CH*CH];
__device__ float g_Np  [(size_t)16*32*4*CH];
__device__ float g_attn[(size_t)NB*NHEAD*CH*CH];
__device__ float g_M   [(size_t)NB*CCH*CCH];

__device__ __forceinline__ uint32_t pack_h2(float lo, float hi) {
  __half2 h = __floats2half2_rn(lo, hi);
  return *(uint32_t*)&h;
}
__device__ __forceinline__ uint32_t pack_hh(__half lo, __half hi) {
  __half2 h = __halves2half2(lo, hi);
  return *(uint32_t*)&h;
}
__device__ __forceinline__ void store2(float* p, float a, float b) {
  *(float2*)p = make_float2(a, b);
}
__device__ __forceinline__ void store2(__half* p, float a, float b) {
  *(uint32_t*)p = pack_h2(a, b);
}
__device__ __forceinline__ void mma_fp16(float* c, const uint32_t* a, const uint32_t* b) {
  asm volatile(
    "mma.sync.aligned.m16n8k16.row.col.f32.f16.f16.f32 "
    "{%0,%1,%2,%3},{%4,%5,%6,%7},{%8,%9},{%0,%1,%2,%3};"
    : "+f"(c[0]), "+f"(c[1]), "+f"(c[2]), "+f"(c[3])
    : "r"(a[0]), "r"(a[1]), "r"(a[2]), "r"(a[3]), "r"(b[0]), "r"(b[1]));
}

// ================ fp16 tensor-core GEMM (R9 proven, verbatim) ===============
#define AST 200
#define BST 136

template <typename OutT>
__global__ __launch_bounds__(256, 1) void gemm1x1_fp16(
    const float* __restrict__ Wm, const float* __restrict__ X,
    OutT* __restrict__ Y, int K,
    size_t wstride, size_t xstride, size_t ystride)
{
  const int b  = blockIdx.z;
  const int m0 = blockIdx.y * 192;
  const int n0 = blockIdx.x * 128;
  const float* Wb = Wm + (size_t)b * wstride;
  const float* Xb = X + (size_t)b * xstride;
  OutT* Yb = Y + (size_t)b * ystride;

  __shared__ uint32_t As2[2][8][AST];
  __shared__ uint32_t Bs2[2][8][BST];

  const int t    = threadIdx.x;
  const int wid  = t >> 5, lane = t & 31;
  const int wm   = wid >> 1, wn = wid & 1;
  const int grp  = lane >> 2, t4 = lane & 3;

  float acc[3][8][4] = {};

  const int bk2 = t >> 5;
  const int bng = (t & 31) * 4;

  float4 pa[3], pb0, pb1;
  #pragma unroll
  for (int i = 0; i < 3; i++) {
    int e = t + i * 256; int row = e >> 2, kf = (e & 3) * 4;
    pa[i] = *(const float4*)&Wb[(size_t)(m0 + row) * K + kf];
  }
  pb0 = *(const float4*)&Xb[(size_t)(2 * bk2    ) * HW + n0 + bng];
  pb1 = *(const float4*)&Xb[(size_t)(2 * bk2 + 1) * HW + n0 + bng];
  #pragma unroll
  for (int i = 0; i < 3; i++) {
    int e = t + i * 256; int row = e >> 2, k2 = (e & 3) * 2;
    As2[0][k2  ][row] = pack_h2(pa[i].x, pa[i].y);
    As2[0][k2+1][row] = pack_h2(pa[i].z, pa[i].w);
  }
  {
    uint4 u = make_uint4(pack_h2(pb0.x, pb1.x), pack_h2(pb0.y, pb1.y),
                         pack_h2(pb0.z, pb1.z), pack_h2(pb0.w, pb1.w));
    *(uint4*)&Bs2[0][bk2][bng] = u;
  }
  __syncthreads();

  int p = 0;
  for (int k0 = 0; k0 < K; k0 += 16) {
    bool more = (k0 + 16) < K;
    if (more) {
      #pragma unroll
      for (int i = 0; i < 3; i++) {
        int e = t + i * 256; int row = e >> 2, kf = (e & 3) * 4;
        pa[i] = *(const float4*)&Wb[(size_t)(m0 + row) * K + k0 + 16 + kf];
      }
      pb0 = *(const float4*)&Xb[(size_t)(k0 + 16 + 2 * bk2    ) * HW + n0 + bng];
      pb1 = *(const float4*)&Xb[(size_t)(k0 + 16 + 2 * bk2 + 1) * HW + n0 + bng];
    }
    {
      uint32_t af[3][4], bf[8][2];
      #pragma unroll
      for (int mt = 0; mt < 3; mt++) {
        int mb = wm * 48 + mt * 16 + grp;
        af[mt][0] = As2[p][t4    ][mb];     af[mt][1] = As2[p][t4    ][mb + 8];
        af[mt][2] = As2[p][t4 + 4][mb];     af[mt][3] = As2[p][t4 + 4][mb + 8];
      }
      #pragma unroll
      for (int nt = 0; nt < 8; nt++) {
        int nb = wn * 64 + nt * 8 + grp;
        bf[nt][0] = Bs2[p][t4][nb]; bf[nt][1] = Bs2[p][t4 + 4][nb];
      }
      #pragma unroll
      for (int mt = 0; mt < 3; mt++)
        #pragma unroll
        for (int nt = 0; nt < 8; nt++)
          mma_fp16(acc[mt][nt], af[mt], bf[nt]);
    }
    if (more) {
      #pragma unroll
      for (int i = 0; i < 3; i++) {
        int e = t + i * 256; int row = e >> 2, k2 = (e & 3) * 2;
        As2[1-p][k2  ][row] = pack_h2(pa[i].x, pa[i].y);
        As2[1-p][k2+1][row] = pack_h2(pa[i].z, pa[i].w);
      }
      uint4 u = make_uint4(pack_h2(pb0.x, pb1.x), pack_h2(pb0.y, pb1.y),
                           pack_h2(pb0.z, pb1.z), pack_h2(pb0.w, pb1.w));
      *(uint4*)&Bs2[1-p][bk2][bng] = u;
    }
    __syncthreads();
    p ^= 1;
  }

  #pragma unroll
  for (int mt = 0; mt < 3; mt++) {
    #pragma unroll
    for (int nt = 0; nt < 8; nt++) {
      int mr = m0 + wm * 48 + mt * 16 + grp;
      int nc = n0 + wn * 64 + nt * 8 + t4 * 2;
      store2(&Yb[(size_t)mr * HW + nc], acc[mt][nt][0], acc[mt][nt][1]);
      store2(&Yb[(size_t)(mr + 8) * HW + nc], acc[mt][nt][2], acc[mt][nt][3]);
    }
  }
}

// ------- conv3 weight transform: W[m][ci*9+tap] -> packed Wp[k2][m] ---------
__global__ __launch_bounds__(256) void wtrans3_k(
    const float* __restrict__ W, uint32_t* __restrict__ Wp)
{
  int e = blockIdx.x * 256 + threadIdx.x;
  if (e >= (CCH*9/2) * CCH) return;
  int k2 = e / CCH, m = e - k2 * CCH;
  int k  = k2 * 2;
  int tap = k / CCH;
  int ci  = k - tap * CCH;
  float a = W[(size_t)m * (CCH*9) + ci * 9 + tap];
  float b = W[(size_t)m * (CCH*9) + (ci + 1) * 9 + tap];
  Wp[(size_t)k2 * CCH + m] = pack_h2(a, b);
}

// ====== fp16 conv3x3, reordered-K implicit GEMM, prepacked weights (R9) =====
__global__ __launch_bounds__(256, 1) void conv3x3_fp16(
    const uint32_t* __restrict__ Wp, const __half* __restrict__ X,
    float* __restrict__ Y)
{
  const int Ktot = CCH * 9;
  const int b = blockIdx.z;
  const int y = blockIdx.x;
  const __half* Xb = X + (size_t)b * CCH * HW;
  float* Yb = Y + (size_t)b * CCH * HW;

  __shared__ uint32_t As2[2][8][AST];
  __shared__ uint32_t Bs2[2][8][BST];

  const int t   = threadIdx.x;
  const int wid = t >> 5, lane = t & 31;
  const int wm  = wid >> 1, wn = wid & 1;
  const int grp = lane >> 2, t4 = lane & 3;

  float acc[3][8][4] = {};

  const int bk2 = t >> 5;
  const int bng = (t & 31) * 4;

  const __half hz = __float2half(0.f);

  auto gatherB = [&](int k0, uint4* u) {
    int kk  = k0 + 2 * bk2;
    int tap = kk / CCH;
    int ci  = kk - tap * CCH;
    int dy  = tap / 3 - 1;
    int dx  = tap - (tap / 3) * 3 - 1;
    int yy  = y + dy;
    __half v0[4], v1[4];
    if (yy >= 0 && yy < WID) {
      const __half* s0 = Xb + (size_t)ci * HW + yy * WID;
      const __half* s1 = s0 + HW;
      #pragma unroll
      for (int j = 0; j < 4; j++) {
        int xx = bng + j + dx;
        bool ok = (xx >= 0) & (xx < WID);
        v0[j] = ok ? s0[xx] : hz;
        v1[j] = ok ? s1[xx] : hz;
      }
    } else {
      #pragma unroll
      for (int j = 0; j < 4; j++) { v0[j] = hz; v1[j] = hz; }
    }
    *u = make_uint4(pack_hh(v0[0], v1[0]), pack_hh(v0[1], v1[1]),
                    pack_hh(v0[2], v1[2]), pack_hh(v0[3], v1[3]));
  };

  uint32_t paw[6];
  uint4 pbu;
  #pragma unroll
  for (int i = 0; i < 6; i++) {
    int e = t + i * 256; int k2l = e / 192, m = e - k2l * 192;
    paw[i] = Wp[(size_t)k2l * CCH + m];
  }
  gatherB(0, &pbu);
  #pragma unroll
  for (int i = 0; i < 6; i++) {
    int e = t + i * 256; int k2l = e / 192, m = e - k2l * 192;
    As2[0][k2l][m] = paw[i];
  }
  *(uint4*)&Bs2[0][bk2][bng] = pbu;
  __syncthreads();

  int p = 0;
  for (int k0 = 0; k0 < Ktot; k0 += 16) {
    bool more = (k0 + 16) < Ktot;
    if (more) {
      int k2base = (k0 + 16) >> 1;
      #pragma unroll
      for (int i = 0; i < 6; i++) {
        int e = t + i * 256; int k2l = e / 192, m = e - k2l * 192;
        paw[i] = Wp[(size_t)(k2base + k2l) * CCH + m];
      }
      gatherB(k0 + 16, &pbu);
    }
    {
      uint32_t af[3][4], bf[8][2];
      #pragma unroll
      for (int mt = 0; mt < 3; mt++) {
        int mb = wm * 48 + mt * 16 + grp;
        af[mt][0] = As2[p][t4    ][mb];     af[mt][1] = As2[p][t4    ][mb + 8];
        af[mt][2] = As2[p][t4 + 4][mb];     af[mt][3] = As2[p][t4 + 4][mb + 8];
      }
      #pragma unroll
      for (int nt = 0; nt < 8; nt++) {
        int nb = wn * 64 + nt * 8 + grp;
        bf[nt][0] = Bs2[p][t4][nb]; bf[nt][1] = Bs2[p][t4 + 4][nb];
      }
      #pragma unroll
      for (int mt = 0; mt < 3; mt++)
        #pragma unroll
        for (int nt = 0; nt < 8; nt++)
          mma_fp16(acc[mt][nt], af[mt], bf[nt]);
    }
    if (more) {
      #pragma unroll
      for (int i = 0; i < 6; i++) {
        int e = t + i * 256; int k2l = e / 192, m = e - k2l * 192;
        As2[1-p][k2l][m] = paw[i];
      }
      *(uint4*)&Bs2[1-p][bk2][bng] = pbu;
    }
    __syncthreads();
    p ^= 1;
  }

  const int n0 = y * 128;
  #pragma unroll
  for (int mt = 0; mt < 3; mt++) {
    #pragma unroll
    for (int nt = 0; nt < 8; nt++) {
      int mr = wm * 48 + mt * 16 + grp;
      int nc = n0 + wn * 64 + nt * 8 + t4 * 2;
      *(float2*)&Yb[(size_t)mr * HW + nc] = make_float2(acc[mt][nt][0], acc[mt][nt][1]);
      *(float2*)&Yb[(size_t)(mr + 8) * HW + nc] = make_float2(acc[mt][nt][2], acc[mt][nt][3]);
    }
  }
}

// ------- depthwise 3x3 (groups = 3C), fp16 in / fp32 out, 8 outputs/thread --
__global__ __launch_bounds__(256) void dwconv8_k(
    const __half* __restrict__ in, const float* __restrict__ w,
    float* __restrict__ out)
{
  size_t i8 = (size_t)blockIdx.x * 256 + threadIdx.x;
  size_t base = i8 * 8;
  int s  = (int)(base & (HW - 1));
  size_t bc = base >> 14;
  int c = (int)(bc % C3);
  int y = s >> 7, x0 = s & 127;
  const float* wp = w + (size_t)c * 9;
  const __half* ip = in + (base - s);
  float w0=wp[0],w1=wp[1],w2=wp[2],w3=wp[3],w4=wp[4],w5=wp[5],w6=wp[6],w7=wp[7],w8=wp[8];
  float a[8] = {};
  #pragma unroll
  for (int dy = -1; dy <= 1; dy++) {
    int yy = y + dy;
    if (yy < 0 || yy >= WID) continue;
    const __half* row = ip + yy * WID;
    uint4 u = *(const uint4*)&row[x0];
    const __half2* h2 = (const __half2*)&u;
    float c8[8];
    #pragma unroll
    for (int j = 0; j < 4; j++) {
      float2 f = __half22float2(h2[j]);
      c8[2*j] = f.x; c8[2*j+1] = f.y;
    }
    float lf = (x0 > 0)   ? __half2float(row[x0 - 1]) : 0.f;
    float rt = (x0 < 120) ? __half2float(row[x0 + 8]) : 0.f;
    float r0, r1, r2;
    if (dy < 0)      { r0 = w0; r1 = w1; r2 = w2; }
    else if (dy==0)  { r0 = w3; r1 = w4; r2 = w5; }
    else             { r0 = w6; r1 = w7; r2 = w8; }
    a[0] += r0*lf + r1*c8[0] + r2*c8[1];
    #pragma unroll
    for (int j = 1; j < 7; j++)
      a[j] += r0*c8[j-1] + r1*c8[j] + r2*c8[j+1];
    a[7] += r0*c8[6] + r1*c8[7] + r2*rt;
  }
  *(float4*)&out[base]     = make_float4(a[0], a[1], a[2], a[3]);
  *(float4*)&out[base + 4] = make_float4(a[4], a[5], a[6], a[7]);
}

// ---- logits: raw Grams Gqk = q k^T, Gck = cn k^T + per-channel norm partials
__global__ __launch_bounds__(256) void logits2_k(
    const float* __restrict__ qkv, const float* __restrict__ cnf,
    float* __restrict__ Gqk, float* __restrict__ Gck, float* __restrict__ Np)
{
  int bh = blockIdx.y; int b = bh >> 2, h = bh & 3;
  int chunk = blockIdx.x;
  int s0 = chunk * 1024;
  const float* Q  = qkv + ((size_t)b*C3 + h*CH) * HW;
  const float* Kp = qkv + ((size_t)b*C3 + CCH + h*CH) * HW;
  const float* Cn = cnf + ((size_t)b*CCH + h*CH) * HW;
  __shared__ float Qs[48][68];
  __shared__ float Ks[48][68];
  __shared__ float Cs[48][68];
  const int t = threadIdx.x;
  const int tx = t & 15, ty = t >> 4;
  float aqk[3][3] = {}, ack[3][3] = {};
  float psq[3] = {}, psk[3] = {}, psc[3] = {}, psd[3] = {};
  for (int sc = 0; sc < 1024; sc += 64) {
    #pragma unroll
    for (int i = 0; i < 3; i++) {
      int e = t + i * 256;
      int row = e >> 4;
      int col = (e & 15) * 4;
      float4 q4 = *(const float4*)&Q [(size_t)row*HW + s0 + sc + col];
      float4 c4 = *(const float4*)&Cn[(size_t)row*HW + s0 + sc + col];
      float4 k4 = *(const float4*)&Kp[(size_t)row*HW + s0 + sc + col];
      *(float4*)&Qs[row][col] = q4;
      *(float4*)&Cs[row][col] = c4;
      *(float4*)&Ks[row][col] = k4;
      psq[i] += q4.x*q4.x + q4.y*q4.y + q4.z*q4.z + q4.w*q4.w;
      psk[i] += k4.x*k4.x + k4.y*k4.y + k4.z*k4.z + k4.w*k4.w;
      psc[i] += c4.x*c4.x + c4.y*c4.y + c4.z*c4.z + c4.w*c4.w;
      psd[i] += q4.x*c4.x + q4.y*c4.y + q4.z*c4.z + q4.w*c4.w;
    }
    __syncthreads();
    #pragma unroll 4
    for (int s = 0; s < 64; s++) {
      float qv0 = Qs[ty*3+0][s], qv1 = Qs[ty*3+1][s], qv2 = Qs[ty*3+2][s];
      float cv0 = Cs[ty*3+0][s], cv1 = Cs[ty*3+1][s], cv2 = Cs[ty*3+2][s];
      float kv0 = Ks[tx*3+0][s], kv1 = Ks[tx*3+1][s], kv2 = Ks[tx*3+2][s];
      aqk[0][0]+=qv0*kv0; aqk[0][1]+=qv0*kv1; aqk[0][2]+=qv0*kv2;
      aqk[1][0]+=qv1*kv0; aqk[1][1]+=qv1*kv1; aqk[1][2]+=qv1*kv2;
      aqk[2][0]+=qv2*kv0; aqk[2][1]+=qv2*kv1; aqk[2][2]+=qv2*kv2;
      ack[0][0]+=cv0*kv0; ack[0][1]+=cv0*kv1; ack[0][2]+=cv0*kv2;
      ack[1][0]+=cv1*kv0; ack[1][1]+=cv1*kv1; ack[1][2]+=cv1*kv2;
      ack[2][0]+=cv2*kv0; ack[2][1]+=cv2*kv1; ack[2][2]+=cv2*kv2;
    }
    __syncthreads();
  }
  size_t gbase = ((size_t)chunk * 32 + bh) * CH * CH;
  #pragma unroll
  for (int i = 0; i < 3; i++)
    #pragma unroll
    for (int j = 0; j < 3; j++) {
      Gqk[gbase + (size_t)(ty*3+i)*CH + tx*3+j] = aqk[i][j];
      Gck[gbase + (size_t)(ty*3+i)*CH + tx*3+j] = ack[i][j];
    }
  #pragma unroll
  for (int i = 0; i < 3; i++) {
    int row = (t + i * 256) >> 4;
    float vq = psq[i], vk = psk[i], vc = psc[i], vd = psd[i];
    #pragma unroll
    for (int o = 8; o > 0; o >>= 1) {
      vq += __shfl_down_sync(0xffffffffu, vq, o, 16);
      vk += __shfl_down_sync(0xffffffffu, vk, o, 16);
      vc += __shfl_down_sync(0xffffffffu, vc, o, 16);
      vd += __shfl_down_sync(0xffffffffu, vd, o, 16);
    }
    if ((t & 15) == 0) {
      size_t nb = (((size_t)chunk * 32 + bh) * 4) * CH;
      Np[nb + 0*CH + row] = vq;
      Np[nb + 1*CH + row] = vk;
      Np[nb + 2*CH + row] = vc;
      Np[nb + 3*CH + row] = vd;
    }
  }
}

// ------ softmax with fused scalars: alpha/beta/invk computed in-register ----
// Per block (row = bh*48 + c): serial ch-order sums match old scalars_k
// exactly (bitwise), so results are identical to the R9 two-kernel path.
__global__ __launch_bounds__(32) void softmax3_k(
    const float* __restrict__ Gqk, const float* __restrict__ Gck,
    const float* __restrict__ Np, const float* __restrict__ temp,
    float* __restrict__ attn)
{
  int row = blockIdx.x;            // bh*48 + c
  int bh = row / CH;
  int c  = row - bh * CH;
  int h  = bh & 3;
  int lane = threadIdx.x;
  float tv = temp[h];
  bool has1 = (lane + 32) < CH;
  float Sq = 0, Sc = 0, Sd = 0;          // for channel c (all lanes redundant)
  float Sk0 = 0, Sk1 = 0;                // for d = lane, lane+32
  float gq0 = 0, gc0 = 0, gq1 = 0, gc1 = 0;
  for (int ch = 0; ch < 16; ch++) {
    size_t nb = (((size_t)ch * 32 + bh) * 4) * CH;
    Sq += Np[nb + 0*CH + c];
    Sc += Np[nb + 2*CH + c];
    Sd += Np[nb + 3*CH + c];
    Sk0 += Np[nb + 1*CH + lane];
    if (has1) Sk1 += Np[nb + 1*CH + lane + 32];
    size_t base = (((size_t)ch*32 + bh)*CH + c)*CH;
    gq0 += Gqk[base + lane]; gc0 += Gck[base + lane];
    if (has1) { gq1 += Gqk[base + lane + 32]; gc1 += Gck[base + lane + 32]; }
  }
  float a  = fmaxf(sqrtf(Sq), EPSV);
  float bb = fmaxf(sqrtf(Sc), EPSV);
  float n2 = Sq/(a*a) + 2.f*Sd/(a*bb) + Sc/(bb*bb);
  float dn = fmaxf(sqrtf(fmaxf(n2, 0.f)), EPSV);
  float al = 1.f / (a * dn);
  float be = 1.f / (bb * dn);
  float ik0 = 1.f / fmaxf(sqrtf(Sk0), EPSV);
  float ik1 = has1 ? (1.f / fmaxf(sqrtf(Sk1), EPSV)) : 0.f;

  float v0 = (al * gq0 + be * gc0) * ik0 * tv;
  float v1 = (al * gq1 + be * gc1) * ik1 * tv;
  float m = has1 ? fmaxf(v0, v1) : v0;
  #pragma unroll
  for (int o = 16; o > 0; o >>= 1) m = fmaxf(m, __shfl_xor_sync(0xffffffffu, m, o));
  float e0 = __expf(v0 - m);
  float e1 = has1 ? __expf(v1 - m) : 0.f;
  float s = e0 + e1;
  #pragma unroll
  for (int o = 16; o > 0; o >>= 1) s += __shfl_xor_sync(0xffffffffu, s, o);
  float inv = 1.f / s;
  attn[(size_t)row*CH + lane] = e0 * inv;
  if (has1) attn[(size_t)row*CH + lane + 32] = e1 * inv;
}

// ---------------- M = P @ blockdiag(attn): per-batch fused proj weights ----
__global__ __launch_bounds__(192) void pa_k(
    const float* __restrict__ P, const float* __restrict__ attn,
    float* __restrict__ M)
{
  int bh = blockIdx.x; int b = bh >> 2, h = bh & 3;
  __shared__ float As[48][49];
  const int t = threadIdx.x;
  for (int e = t; e < 48*48; e += 192)
    As[e / 48][e % 48] = attn[(size_t)bh * CH * CH + e];
  __syncthreads();
  float pr[48];
  #pragma unroll
  for (int c = 0; c < 48; c++)
    pr[c] = P[(size_t)t * CCH + h * CH + c];
  #pragma unroll 4
  for (int d = 0; d < 48; d++) {
    float s = 0.f;
    #pragma unroll
    for (int c = 0; c < 48; c++) s += pr[c] * As[c][d];
    M[((size_t)b * CCH + t) * CCH + h * CH + d] = s;
  }
}

// ---------------- launch -----------------------------------------------------
extern "C" void kernel_launch(void* const* d_in, const int* in_sizes, int n_in,
                              void* d_out, int out_size)
{
  const float* x        = (const float*)d_in[0];
  const float* cn       = (const float*)d_in[1];
  const float* cn_w1    = (const float*)d_in[2];
  const float* cn_w3    = (const float*)d_in[3];
  const float* qkv_w    = (const float*)d_in[4];
  const float* qkv_dw_w = (const float*)d_in[5];
  const float* proj_w   = (const float*)d_in[6];
  const float* temp     = (const float*)d_in[7];
  float* out = (float*)d_out;

  __half *cn1, *qkv1;
  uint32_t *Wp3;
  float *cnf, *qkv, *Gqk, *Gck, *Np, *at, *Mw;
  cudaGetSymbolAddress((void**)&cn1,  g_cn1);
  cudaGetSymbolAddress((void**)&cnf,  g_cnf);
  cudaGetSymbolAddress((void**)&qkv1, g_qkv1);
  cudaGetSymbolAddress((void**)&qkv,  g_qkv);
  cudaGetSymbolAddress((void**)&Wp3,  g_Wp3);
  cudaGetSymbolAddress((void**)&Gqk,  g_Gqk);
  cudaGetSymbolAddress((void**)&Gck,  g_Gck);
  cudaGetSymbolAddress((void**)&Np,   g_Np);
  cudaGetSymbolAddress((void**)&at,   g_attn);
  cudaGetSymbolAddress((void**)&Mw,   g_M);

  dim3 g1(HW/128, 1, NB);
  gemm1x1_fp16<__half><<<g1, 256>>>(cn_w1, cn, cn1, CCH,
                                    0, (size_t)CCH*HW, (size_t)CCH*HW);
  wtrans3_k<<<((CCH*9/2)*CCH + 255)/256, 256>>>(cn_w3, Wp3);
  conv3x3_fp16<<<g1, 256>>>(Wp3, cn1, cnf);

  dim3 g2(HW/128, 3, NB);
  gemm1x1_fp16<__half><<<g2, 256>>>(qkv_w, x, qkv1, CCH,
                                    0, (size_t)CCH*HW, (size_t)C3*HW);

  size_t ndw8 = (size_t)NB * C3 * HW / 8;
  dwconv8_k<<<(unsigned)(ndw8 / 256), 256>>>(qkv1, qkv_dw_w, qkv);

  logits2_k<<<dim3(16, NB*NHEAD), 256>>>(qkv, cnf, Gqk, Gck, Np);
  softmax3_k<<<NB*NHEAD*CH, 32>>>(Gqk, Gck, Np, temp, at);
  pa_k<<<NB*NHEAD, 192>>>(proj_w, at, Mw);

  // fused (attn@v + proj): out_b = M_b @ v_b
  gemm1x1_fp16<float><<<g1, 256>>>(Mw, qkv + (size_t)2*CCH*HW, out, CCH,
                                   (size_t)CCH*CCH, (size_t)C3*HW, (size_t)CCH*HW);
}